// round 12
// baseline (speedup 1.0000x reference)
#include <cuda_runtime.h>
#include <cuda_fp16.h>
#include <cstdint>
#include <type_traits>

#define BB      8
#define LL      2048
#define DIMM    768
#define DIN     1536
#define DSTATE  16
#define DTRANK  48
#define NROWS   (BB * LL)              // 16384
#define XPROJ   (DTRANK + 2 * DSTATE)  // 80
#define DTPADK  64                     // dt_proj K padded 48 -> 64
#define NSEG    8                      // scan segments
#define SEGL    (LL / NSEG)            // 256 steps per segment

// ---------------- scratch (static device globals; no allocation allowed) ---
__device__ float g_xdbl[(size_t)NROWS * XPROJ];
// segmented-scan state buffers: layout [b][seg][s][DIN]
__device__ float g_Hseg[(size_t)BB * NSEG * DSTATE * DIN];
__device__ float g_Eseg[(size_t)BB * NSEG * DSTATE * DIN];
__device__ float g_H0  [(size_t)BB * NSEG * DSTATE * DIN];

// fp16 tensors (plain row-major)
__device__ __align__(128) __half g_ax[(size_t)NROWS * DIMM];        // LN out
__device__ __align__(128) __half g_wi[(size_t)(2*DIN) * DIMM];      // W_in
__device__ __align__(128) __half g_xz16[(size_t)NROWS * 2 * DIN];   // in_proj out
__device__ __align__(128) __half g_xc16[(size_t)NROWS * DIN];       // conv out
__device__ __align__(128) __half g_dt16[(size_t)NROWS * DIN];       // dt
__device__ __align__(128) __half g_ay[(size_t)NROWS * DIN];         // scan out
__device__ __align__(128) __half g_wo[(size_t)DIMM * DIN];          // W_out
__device__ __align__(128) __half g_wx[(size_t)128 * DIN];           // W_xp padded
__device__ __align__(128) __half g_xd[(size_t)NROWS * DTPADK];      // dt input
__device__ __align__(128) __half g_wd[(size_t)DIN * DTPADK];        // W_dt padded

// ======================== PTX helpers ============================
__device__ __forceinline__ uint32_t smem_u32(const void* p) {
    uint32_t a;
    asm("{ .reg .u64 t; cvta.to.shared.u64 t, %1; cvt.u32.u64 %0, t; }"
        : "=r"(a) : "l"(p));
    return a;
}
__device__ __forceinline__ void cp16(uint32_t dst, const void* src) {
    asm volatile("cp.async.cg.shared.global [%0], [%1], 16;" :: "r"(dst), "l"(src));
}
__device__ __forceinline__ void cp_commit() {
    asm volatile("cp.async.commit_group;" ::: "memory");
}
#define CP_WAIT(n) asm volatile("cp.async.wait_group %0;" :: "n"(n) : "memory")

#define LDSM4(r0, r1, r2, r3, addr) \
    asm volatile("ldmatrix.sync.aligned.m8n8.x4.shared.b16 {%0,%1,%2,%3}, [%4];" \
                 : "=r"(r0), "=r"(r1), "=r"(r2), "=r"(r3) : "r"(addr))
#define LDSM2(r0, r1, addr) \
    asm volatile("ldmatrix.sync.aligned.m8n8.x2.shared.b16 {%0,%1}, [%2];" \
                 : "=r"(r0), "=r"(r1) : "r"(addr))
#define MMA16816(d, a, b) \
    asm volatile("mma.sync.aligned.m16n8k16.row.col.f32.f16.f16.f32 " \
                 "{%0,%1,%2,%3},{%4,%5,%6,%7},{%8,%9},{%0,%1,%2,%3};" \
                 : "+f"((d)[0]), "+f"((d)[1]), "+f"((d)[2]), "+f"((d)[3]) \
                 : "r"((a)[0]), "r"((a)[1]), "r"((a)[2]), "r"((a)[3]), \
                   "r"((b)[0]), "r"((b)[1]))

__device__ __forceinline__ float softplusf(float v) {
    return (v > 20.f) ? v : log1pf(__expf(v));
}
__device__ __forceinline__ uint32_t pack_h2(float a, float b) {
    __half2 h2 = __floats2half2_rn(a, b);
    return *reinterpret_cast<uint32_t*>(&h2);
}

// =========================== pack kernels ==========================
__global__ void pack_h(const float* __restrict__ in,
                       uint4* __restrict__ out, long long total8)
{
    const long long idx = (long long)blockIdx.x * blockDim.x + threadIdx.x;
    if (idx >= total8) return;
    const float* p = in + idx * 8;
    uint32_t u[4];
#pragma unroll
    for (int j = 0; j < 4; j++) u[j] = pack_h2(p[2*j], p[2*j + 1]);
    out[idx] = make_uint4(u[0], u[1], u[2], u[3]);
}

__global__ void pack_pad(const float* __restrict__ in,
                         __half* __restrict__ out,
                         int R, int K, int Rp, int Kp)
{
    const int idx = blockIdx.x * blockDim.x + threadIdx.x;
    if (idx >= Rp * Kp) return;
    const int r = idx / Kp, k = idx % Kp;
    float v = (r < R && k < K) ? in[(size_t)r * K + k] : 0.f;
    out[idx] = __float2half_rn(v);
}

// ================== mma.sync fp16 single-pass TN GEMM =====================
// 2-stage double buffer, 2 CTAs/SM (round-10/11 proven structure).
// EPI 0: store fp16 (Ch).      EPI 1: softplus(acc + bias[col]) -> fp16 (Ch).
// EPI 2: mask[m]*(X+acc) -> fp32 (Cf).
// EPI 3: fp32 (col<Ntot) into Cf + fp16 of cols<48 (zeros 48..63) into aux.
#define MM_STG_ROW   40
#define MM_BUF       (128 * 80)
#define MM_STAGE     (2 * MM_BUF)
#define MM_NSTG      2
#define MM_SMEM      (MM_NSTG * MM_STAGE)   // 40960 B

template<int EPI>
__global__ __launch_bounds__(256, 2)
void tgemm(const __half* __restrict__ A, const __half* __restrict__ B,
           float* __restrict__ Cf, __half* __restrict__ Ch,
           int ldc, int K, int Ntot,
           const float* __restrict__ bias,
           const float* __restrict__ X, const int* __restrict__ mask,
           __half* __restrict__ aux)
{
    extern __shared__ char smem[];
    const uint32_t sBase = smem_u32(smem);

    const int tid  = threadIdx.x;
    const int wid  = tid >> 5;
    const int lane = tid & 31;
    const int wm   = wid & 1;
    const int wn   = wid >> 1;
    const int m0   = blockIdx.y * 128;
    const int n0   = blockIdx.x * 128;
    const int NK   = K / 32;

    auto load_stage = [&](int c, int slot) {
        const uint32_t sb = sBase + slot * MM_STAGE;
        const int k0 = c * 32;
#pragma unroll
        for (int h = 0; h < 2; h++) {
            const int ch  = tid + h * 256;
            const int row = ch >> 2;
            const int kc  = ch & 3;
            const uint32_t doff = row * 80 + kc * 16;
            cp16(sb + doff,          A + (size_t)(m0 + row) * K + k0 + kc * 8);
            cp16(sb + MM_BUF + doff, B + (size_t)(n0 + row) * K + k0 + kc * 8);
        }
    };

    float acc[4][4][4];
#pragma unroll
    for (int i = 0; i < 4; i++)
#pragma unroll
        for (int j = 0; j < 4; j++)
#pragma unroll
            for (int r = 0; r < 4; r++) acc[i][j][r] = 0.f;

    load_stage(0, 0); cp_commit();

    const int aRowB = wm * 64 + ((lane >> 3) & 1) * 8 + (lane & 7);
    const int aKB   = (lane >> 4) * 8;
    const int bRowB = wn * 32 + (lane & 7);
    const int bKB   = ((lane >> 3) & 1) * 8;

    for (int c = 0; c < NK; c++) {
        if (c + 1 < NK) load_stage(c + 1, (c + 1) & 1);
        cp_commit();
        CP_WAIT(1);
        __syncthreads();
        const uint32_t sb = sBase + (c & 1) * MM_STAGE;

#pragma unroll
        for (int kk = 0; kk < 2; kk++) {
            uint32_t ah[4][4], bh[4][2];
#pragma unroll
            for (int mi = 0; mi < 4; mi++) {
                const uint32_t ad = sb + ((aRowB + mi * 16) * MM_STG_ROW
                                          + aKB + kk * 16) * 2;
                LDSM4(ah[mi][0], ah[mi][1], ah[mi][2], ah[mi][3], ad);
            }
#pragma unroll
            for (int ni = 0; ni < 4; ni++) {
                const uint32_t bd = sb + MM_BUF + ((bRowB + ni * 8) * MM_STG_ROW
                                                   + bKB + kk * 16) * 2;
                LDSM2(bh[ni][0], bh[ni][1], bd);
            }
#pragma unroll
            for (int mi = 0; mi < 4; mi++)
#pragma unroll
                for (int ni = 0; ni < 4; ni++)
                    MMA16816(acc[mi][ni], ah[mi], bh[ni]);
        }
        __syncthreads();
    }

    const int rq = lane >> 2;
    const int cq = (lane & 3) * 2;
#pragma unroll
    for (int mi = 0; mi < 4; mi++) {
        const int r0 = m0 + wm * 64 + mi * 16 + rq;
        const int r1 = r0 + 8;
        float mf0 = 1.f, mf1 = 1.f;
        if (EPI == 2) { mf0 = (float)mask[r0]; mf1 = (float)mask[r1]; }
#pragma unroll
        for (int ni = 0; ni < 4; ni++) {
            const int cc = n0 + wn * 32 + ni * 8 + cq;
            float v0 = acc[mi][ni][0], v1 = acc[mi][ni][1];
            float v2 = acc[mi][ni][2], v3 = acc[mi][ni][3];
            if (EPI == 1) {
                const float b0 = bias[cc], b1 = bias[cc + 1];
                v0 = softplusf(v0 + b0); v1 = softplusf(v1 + b1);
                v2 = softplusf(v2 + b0); v3 = softplusf(v3 + b1);
            } else if (EPI == 2) {
                const float* x0 = X + (size_t)r0 * ldc + cc;
                const float* x1 = X + (size_t)r1 * ldc + cc;
                v0 = mf0 * (x0[0] + v0); v1 = mf0 * (x0[1] + v1);
                v2 = mf1 * (x1[0] + v2); v3 = mf1 * (x1[1] + v3);
            }
            if (EPI == 0 || EPI == 1) {
                *(uint32_t*)(Ch + (size_t)r0 * ldc + cc) = pack_h2(v0, v1);
                *(uint32_t*)(Ch + (size_t)r1 * ldc + cc) = pack_h2(v2, v3);
            } else if (EPI == 2) {
                *(float2*)(Cf + (size_t)r0 * ldc + cc) = make_float2(v0, v1);
                *(float2*)(Cf + (size_t)r1 * ldc + cc) = make_float2(v2, v3);
            } else {   // EPI 3
                if (cc + 1 < Ntot) {
                    *(float2*)(Cf + (size_t)r0 * ldc + cc) = make_float2(v0, v1);
                    *(float2*)(Cf + (size_t)r1 * ldc + cc) = make_float2(v2, v3);
                }
#pragma unroll
                for (int j = 0; j < 2; j++) {
                    const int col = cc + j;
                    if (col < DTPADK) {
                        const float a0 = (col < DTRANK) ? ((j == 0) ? v0 : v1) : 0.f;
                        const float a1 = (col < DTRANK) ? ((j == 0) ? v2 : v3) : 0.f;
                        aux[(size_t)r0 * DTPADK + col] = __float2half_rn(a0);
                        aux[(size_t)r1 * DTPADK + col] = __float2half_rn(a1);
                    }
                }
            }
        }
    }
}

// --------------------------- LayerNorm + fp16 pack -------------------------
__global__ void ln_kernel(const float* __restrict__ x,
                          const int*   __restrict__ mask,
                          const float* __restrict__ g,
                          const float* __restrict__ b,
                          __half* __restrict__ xh)
{
    const int row = blockIdx.x;
    const int t   = threadIdx.x;
    const float* xr = x + (size_t)row * DIMM;

    float v[3];
    float s = 0.f, s2 = 0.f;
#pragma unroll
    for (int j = 0; j < 3; j++) {
        v[j] = xr[t + j * 256];
        s  += v[j];
        s2 += v[j] * v[j];
    }
    __shared__ float red[2][8];
#pragma unroll
    for (int o = 16; o > 0; o >>= 1) {
        s  += __shfl_xor_sync(0xffffffffu, s,  o);
        s2 += __shfl_xor_sync(0xffffffffu, s2, o);
    }
    if ((t & 31) == 0) { red[0][t >> 5] = s; red[1][t >> 5] = s2; }
    __syncthreads();
    float ts = 0.f, ts2 = 0.f;
#pragma unroll
    for (int j = 0; j < 8; j++) { ts += red[0][j]; ts2 += red[1][j]; }

    const float mu   = ts * (1.0f / DIMM);
    const float var  = ts2 * (1.0f / DIMM) - mu * mu;
    const float rstd = rsqrtf(var + 1e-5f);
    const float mf   = (float)mask[row];

#pragma unroll
    for (int j = 0; j < 3; j++) {
        const int c = t + j * 256;
        const float o = ((v[j] - mu) * rstd * g[c] + b[c]) * mf;
        xh[(size_t)row * DIMM + c] = __float2half_rn(o);
    }
}

// --------------- depthwise causal conv4 + SiLU (fp16 in/out) ---------------
__global__ void conv_silu(const __half* __restrict__ xz,
                          const float* __restrict__ w,
                          const float* __restrict__ bias,
                          __half* __restrict__ xch)
{
    const long long idx = (long long)blockIdx.x * blockDim.x + threadIdx.x;
    if (idx >= (long long)NROWS * DIN) return;
    const int d = (int)(idx % DIN);
    const int i = (int)(idx / DIN);
    const int l = i % LL;

    float s = bias[d];
    const float* wp = w + d * 4;
#pragma unroll
    for (int j = 0; j < 4; j++) {
        const int ll = l - 3 + j;
        if (ll >= 0)
            s = fmaf(wp[j], __half2float(xz[(size_t)(i - 3 + j) * (2 * DIN) + d]), s);
    }
    const float sig = 1.f / (1.f + __expf(-s));
    xch[idx] = __float2half_rn(s * sig);
}

// ======================= segmented selective scan ==========================
// fp16 staged inputs (dt, xc, z), fp32 xdbl (B,C), fp32 recurrence.
// per-slot smem layout (bytes): [0,256) dt | [256,512) xc | [512,768) z |
//                               [768,896) B,C fp32
#define SSTAGE   8
#define SLOT_B   896

template<int PHASE>
__global__ __launch_bounds__(128)
void scan_seg(const __half* __restrict__ dt,
              const __half* __restrict__ xc,
              const __half* __restrict__ xz,
              const float* __restrict__ xdbl,
              const float* __restrict__ A_log,
              const float* __restrict__ Dp,
              float* __restrict__ Hseg,
              float* __restrict__ Eseg,
              const float* __restrict__ H0,
              __half* __restrict__ yh)
{
    __shared__ __align__(16) char sbuf[SSTAGE][SLOT_B];

    const int bx    = blockIdx.x;
    const int b     = bx / ((DIN / 128) * NSEG);
    const int rem   = bx % ((DIN / 128) * NSEG);
    const int chunk = rem / NSEG;
    const int seg   = rem % NSEG;
    const int t     = threadIdx.x;
    const int d     = chunk * 128 + t;
    const size_t rowbase = (size_t)b * LL + (size_t)seg * SEGL;

    float a[DSTATE];
#pragma unroll
    for (int s = 0; s < DSTATE; s++) a[s] = -__expf(A_log[d * DSTATE + s]);

    bool fast = true;
#pragma unroll
    for (int s = 1; s < DSTATE; s++) {
        const float ideal = a[0] * (float)(s + 1);
        if (fabsf(a[s] - ideal) > 1e-4f * fabsf(ideal)) fast = false;
    }
    fast = __syncthreads_and(fast ? 1 : 0);

    const float LOG2E = 1.44269504088896f;
    const float c1 = a[0] * LOG2E;
    float cs[DSTATE];
#pragma unroll
    for (int s = 0; s < DSTATE; s++) cs[s] = a[s] * LOG2E;
    const float dpv = (PHASE == 1) ? Dp[d] : 0.f;

    float h[DSTATE];
    float Ecum[DSTATE];
    const size_t stOff = ((size_t)(b * NSEG + seg) * DSTATE) * DIN + d;
    if (PHASE == 0) {
#pragma unroll
        for (int s = 0; s < DSTATE; s++) { h[s] = 0.f; Ecum[s] = 1.f; }
    } else {
#pragma unroll
        for (int s = 0; s < DSTATE; s++) h[s] = H0[stOff + (size_t)s * DIN];
    }

    const int role = t >> 5;
    const int lane = t & 31;

    auto issue = [&](int tt) {
        const int slot = tt & (SSTAGE - 1);
        const size_t row = rowbase + tt;
        const void* gp = nullptr;
        int soff = 0;
        bool active = false;
        if (role == 0 && lane < 16)      { gp = dt + row * DIN + chunk * 128 + lane * 8;
                                           soff = lane * 16;       active = true; }
        else if (role == 1 && lane < 16) { gp = xc + row * DIN + chunk * 128 + lane * 8;
                                           soff = 256 + lane * 16; active = true; }
        else if (role == 2 && lane < 16) { gp = xz + row * (2 * DIN) + DIN + chunk * 128 + lane * 8;
                                           soff = 512 + lane * 16; active = (PHASE == 1); }
        else if (role == 3 && lane < 8)  { gp = xdbl + row * XPROJ + DTRANK + lane * 4;
                                           soff = 768 + lane * 16; active = true; }
        if (active)
            cp16((uint32_t)__cvta_generic_to_shared(&sbuf[slot][soff]), gp);
        cp_commit();
    };

    for (int tt = 0; tt < SSTAGE - 1; tt++) issue(tt);

    auto run = [&](auto fastc) {
        constexpr bool FAST = decltype(fastc)::value;
        for (int tt = 0; tt < SEGL; tt++) {
            CP_WAIT(SSTAGE - 2);
            __syncthreads();
            if (tt + SSTAGE - 1 < SEGL) issue(tt + SSTAGE - 1);

            const int slot = tt & (SSTAGE - 1);
            const __half* sh = (const __half*)sbuf[slot];
            const float u  = __half2float(sh[t]);
            const float xv = __half2float(sh[128 + t]);
            const float* bc = (const float*)(sbuf[slot] + 768);
            float Bv[DSTATE], Cv[DSTATE];
#pragma unroll
            for (int q = 0; q < 4; q++) {
                float4 vb = *(const float4*)(bc + q * 4);
                Bv[q*4+0] = vb.x; Bv[q*4+1] = vb.y; Bv[q*4+2] = vb.z; Bv[q*4+3] = vb.w;
                if (PHASE == 1) {
                    float4 vc = *(const float4*)(bc + 16 + q * 4);
                    Cv[q*4+0] = vc.x; Cv[q*4+1] = vc.y; Cv[q*4+2] = vc.z; Cv[q*4+3] = vc.w;
                }
            }

            float e[DSTATE];
            if (FAST) {
                const float r = exp2f(u * c1);
                e[0]  = r;
                e[1]  = r * r;
                e[3]  = e[1] * e[1];
                e[7]  = e[3] * e[3];
                e[15] = e[7] * e[7];
                e[2]  = e[1] * r;
                e[4]  = e[3] * r;     e[5]  = e[3] * e[1];  e[6]  = e[3] * e[2];
                e[8]  = e[7] * r;     e[9]  = e[7] * e[1];  e[10] = e[7] * e[2];
                e[11] = e[7] * e[3];  e[12] = e[7] * e[4];  e[13] = e[7] * e[5];
                e[14] = e[7] * e[6];
            } else {
#pragma unroll
                for (int s = 0; s < DSTATE; s++) e[s] = exp2f(u * cs[s]);
            }

            const float ux = u * xv;
            if (PHASE == 0) {
#pragma unroll
                for (int s = 0; s < DSTATE; s++) {
                    h[s]    = fmaf(e[s], h[s], ux * Bv[s]);
                    Ecum[s] = Ecum[s] * e[s];
                }
            } else {
                const float zv = __half2float(sh[256 + t]);
                float y0 = 0.f, y1 = 0.f, y2 = 0.f, y3 = 0.f;
#pragma unroll
                for (int s = 0; s < DSTATE; s += 4) {
                    h[s+0] = fmaf(e[s+0], h[s+0], ux * Bv[s+0]);
                    h[s+1] = fmaf(e[s+1], h[s+1], ux * Bv[s+1]);
                    h[s+2] = fmaf(e[s+2], h[s+2], ux * Bv[s+2]);
                    h[s+3] = fmaf(e[s+3], h[s+3], ux * Bv[s+3]);
                    y0 = fmaf(h[s+0], Cv[s+0], y0);
                    y1 = fmaf(h[s+1], Cv[s+1], y1);
                    y2 = fmaf(h[s+2], Cv[s+2], y2);
                    y3 = fmaf(h[s+3], Cv[s+3], y3);
                }
                float yt = (y0 + y1) + (y2 + y3);
                yt = fmaf(xv, dpv, yt);
                const float sig = 1.f / (1.f + __expf(-zv));
                const float out = yt * (zv * sig);
                yh[(rowbase + tt) * DIN + chunk * 128 + t] = __float2half_rn(out);
            }
        }
    };

    if (fast) run(std::true_type{});
    else      run(std::false_type{});

    if (PHASE == 0) {
#pragma unroll
        for (int s = 0; s < DSTATE; s++) {
            Hseg[stOff + (size_t)s * DIN] = h[s];
            Eseg[stOff + (size_t)s * DIN] = Ecum[s];
        }
    }
}

// sequential composition across segments: H0[b][seg] = state entering segment
__global__ void scan_combine(const float* __restrict__ Hseg,
                             const float* __restrict__ Eseg,
                             float* __restrict__ H0)
{
    const int idx = blockIdx.x * blockDim.x + threadIdx.x;
    if (idx >= BB * DIN) return;
    const int b = idx / DIN, d = idx % DIN;
    float h[DSTATE];
#pragma unroll
    for (int s = 0; s < DSTATE; s++) h[s] = 0.f;
    for (int seg = 0; seg < NSEG; seg++) {
        const size_t o = ((size_t)(b * NSEG + seg) * DSTATE) * DIN + d;
#pragma unroll
        for (int s = 0; s < DSTATE; s++) {
            const size_t os = o + (size_t)s * DIN;
            H0[os] = h[s];
            h[s] = fmaf(Eseg[os], h[s], Hseg[os]);
        }
    }
}

// ------------------------------------------------------------------- launch
extern "C" void kernel_launch(void* const* d_in, const int* in_sizes, int n_in,
                              void* d_out, int out_size)
{
    const float* x      = (const float*)d_in[0];
    const int*   mask   = (const int*)  d_in[1];
    const float* ln_g   = (const float*)d_in[2];
    const float* ln_b   = (const float*)d_in[3];
    const float* W_in   = (const float*)d_in[4];
    const float* conv_w = (const float*)d_in[5];
    const float* conv_b = (const float*)d_in[6];
    const float* W_xp   = (const float*)d_in[7];
    const float* W_dt   = (const float*)d_in[8];
    const float* b_dt   = (const float*)d_in[9];
    const float* A_log  = (const float*)d_in[10];
    const float* Dp     = (const float*)d_in[11];
    const float* W_out  = (const float*)d_in[12];
    float* out = (float*)d_out;

    static float *p_xdbl = nullptr, *p_Hs, *p_Es, *p_H0;
    static __half *p_ax, *p_wi, *p_xz, *p_xc, *p_dt, *p_ay, *p_wo, *p_wx, *p_xd, *p_wd;
    if (!p_xdbl) {
        cudaGetSymbolAddress((void**)&p_xdbl, g_xdbl);
        cudaGetSymbolAddress((void**)&p_Hs,   g_Hseg);
        cudaGetSymbolAddress((void**)&p_Es,   g_Eseg);
        cudaGetSymbolAddress((void**)&p_H0,   g_H0);
        cudaGetSymbolAddress((void**)&p_ax,   g_ax);
        cudaGetSymbolAddress((void**)&p_wi,   g_wi);
        cudaGetSymbolAddress((void**)&p_xz,   g_xz16);
        cudaGetSymbolAddress((void**)&p_xc,   g_xc16);
        cudaGetSymbolAddress((void**)&p_dt,   g_dt16);
        cudaGetSymbolAddress((void**)&p_ay,   g_ay);
        cudaGetSymbolAddress((void**)&p_wo,   g_wo);
        cudaGetSymbolAddress((void**)&p_wx,   g_wx);
        cudaGetSymbolAddress((void**)&p_xd,   g_xd);
        cudaGetSymbolAddress((void**)&p_wd,   g_wd);
        cudaFuncSetAttribute(tgemm<0>, cudaFuncAttributeMaxDynamicSharedMemorySize, MM_SMEM);
        cudaFuncSetAttribute(tgemm<1>, cudaFuncAttributeMaxDynamicSharedMemorySize, MM_SMEM);
        cudaFuncSetAttribute(tgemm<2>, cudaFuncAttributeMaxDynamicSharedMemorySize, MM_SMEM);
        cudaFuncSetAttribute(tgemm<3>, cudaFuncAttributeMaxDynamicSharedMemorySize, MM_SMEM);
    }

    // 1. LayerNorm + mask + fp16 pack
    ln_kernel<<<NROWS, 256>>>(x, mask, ln_g, ln_b, p_ax);

    // 2. pack weights
    {
        long long nW = (long long)(2 * DIN) * DIMM / 8;
        pack_h<<<(unsigned)((nW + 255) / 256), 256>>>(W_in, (uint4*)p_wi, nW);
        long long nO = (long long)DIMM * DIN / 8;
        pack_h<<<(unsigned)((nO + 255) / 256), 256>>>(W_out, (uint4*)p_wo, nO);
        pack_pad<<<(128 * DIN + 255) / 256, 256>>>(W_xp, p_wx, XPROJ, DIN, 128, DIN);
        pack_pad<<<(DIN * DTPADK + 255) / 256, 256>>>(W_dt, p_wd, DIN, DTRANK, DIN, DTPADK);
    }

    // 3. in_proj: xz(fp16) = xn @ W_in^T   (16384 x 3072, K=768)
    {
        dim3 g((2 * DIN) / 128, NROWS / 128);
        tgemm<0><<<g, 256, MM_SMEM>>>(p_ax, p_wi, nullptr, p_xz,
                                      2 * DIN, DIMM, 2 * DIN,
                                      nullptr, nullptr, nullptr, nullptr);
    }

    // 4. depthwise causal conv + SiLU (fp16 in/out)
    {
        const long long n = (long long)NROWS * DIN;
        conv_silu<<<(unsigned)((n + 255) / 256), 256>>>(p_xz, conv_w, conv_b, p_xc);
    }

    // 5. x_proj: xdbl(fp32) = xc @ W_xp^T (N pad 80->128) + dt-input fp16 aux
    {
        dim3 g(1, NROWS / 128);
        tgemm<3><<<g, 256, MM_SMEM>>>(p_xc, p_wx, p_xdbl, nullptr,
                                      XPROJ, DIN, XPROJ,
                                      nullptr, nullptr, nullptr, p_xd);
    }

    // 6. dt_proj + softplus -> fp16 dt (K padded 48->64)
    {
        dim3 g(DIN / 128, NROWS / 128);
        tgemm<1><<<g, 256, MM_SMEM>>>(p_xd, p_wd, nullptr, p_dt,
                                      DIN, DTPADK, DIN,
                                      b_dt, nullptr, nullptr, nullptr);
    }

    // 7. segmented selective scan (fp16 inputs, fp32 recurrence)
    {
        const int nblk = BB * (DIN / 128) * NSEG;   // 768
        scan_seg<0><<<nblk, 128>>>(p_dt, p_xc, p_xz, p_xdbl, A_log, Dp,
                                   p_Hs, p_Es, nullptr, nullptr);
        scan_combine<<<(BB * DIN + 255) / 256, 256>>>(p_Hs, p_Es, p_H0);
        scan_seg<1><<<nblk, 128>>>(p_dt, p_xc, p_xz, p_xdbl, A_log, Dp,
                                   nullptr, nullptr, p_H0, p_ay);
    }

    // 8. out_proj + residual + mask -> fp32 out
    {
        dim3 g(DIMM / 128, NROWS / 128);
        tgemm<2><<<g, 256, MM_SMEM>>>(p_ay, p_wo, out, nullptr,
                                      DIMM, DIN, DIMM,
                                      nullptr, x, mask, nullptr);
    }
}